// round 5
// baseline (speedup 1.0000x reference)
#include <cuda_runtime.h>
#include <cuda_bf16.h>
#include <cstdint>
#include <math.h>

#define N_CLASS 50257
#define EMB 256
#define HID 512
#define BATCH 128
#define SEQ 256
#define NG 2048   // 4*HID packed gate columns (col = h*4 + g; g: 0=i,1=f,2=cand,3=o)
#define KSPLIT 8
#define NBLK 128  // persistent grid (<=148 SMs -> co-resident; spin barrier safe)

// -------- device scratch (static globals; no cudaMalloc allowed) --------
__device__ float g_Wx[EMB * NG];                       // packed x-weights [k][h*4+g]
__device__ float g_Wh[HID * NG];                       // packed h-weights [k][h*4+g]
__device__ float g_bias[NG];                           // packed biases
__device__ float g_Gx[(size_t)SEQ * BATCH * NG];       // precomputed x-gates+bias
__device__ float g_part[KSPLIT * BATCH * NG];          // split-K partials
__device__ float g_HT[2][HID * BATCH];                 // TRANSPOSED hidden state [h][b], double-buffered

// -------- grid barrier state --------
__device__ volatile unsigned g_bar_gen;
__device__ unsigned g_bar_cnt;

// -------- f32x2 helpers (exact fp32, 2 FMA/instr) --------
typedef unsigned long long u64;
__device__ __forceinline__ u64 pack2(float lo, float hi) {
    u64 r; asm("mov.b64 %0,{%1,%2};" : "=l"(r) : "f"(lo), "f"(hi)); return r;
}
__device__ __forceinline__ void fma2(u64 &d, u64 a, u64 b) {
    asm("fma.rn.f32x2 %0,%1,%2,%0;" : "+l"(d) : "l"(a), "l"(b));
}
__device__ __forceinline__ float2 unpack2(u64 v) {
    float2 r; asm("mov.b64 {%0,%1},%2;" : "=f"(r.x), "=f"(r.y) : "l"(v)); return r;
}
// fast activations: MUFU EX2/RCP based, rel err ~2e-7 (harmless vs 1e-3 threshold)
__device__ __forceinline__ float fsig(float x)  { return __fdividef(1.f, 1.f + __expf(-x)); }
__device__ __forceinline__ float ftanh(float x) { return 1.f - __fdividef(2.f, __expf(2.f * x) + 1.f); }

__device__ __forceinline__ void grid_bar() {
    __syncthreads();
    if (threadIdx.x == 0) {
        __threadfence();
        unsigned gen = g_bar_gen;
        if (atomicAdd(&g_bar_cnt, 1u) == NBLK - 1u) {
            g_bar_cnt = 0;
            __threadfence();
            g_bar_gen = gen + 1u;
        } else {
            while (g_bar_gen == gen) { __nanosleep(32); }
            __threadfence();   // acquire: other CTAs' data writes now visible
        }
    }
    __syncthreads();
}

// -------- weight packing: col = h*4 + {i,f,c,o} --------
__global__ __launch_bounds__(256) void pack_kernel(
    const float* __restrict__ Wxi, const float* __restrict__ Wxf,
    const float* __restrict__ Wxo, const float* __restrict__ Wxc,
    const float* __restrict__ Whi, const float* __restrict__ Whf,
    const float* __restrict__ Who, const float* __restrict__ Whc,
    const float* __restrict__ bi,  const float* __restrict__ bf,
    const float* __restrict__ bo,  const float* __restrict__ bc)
{
    int tid = blockIdx.x * 256 + threadIdx.x;   // 0 .. 512*512-1
    int k = tid >> 9, h = tid & 511;
    int n = h * 4;
    g_Wh[k * NG + n + 0] = Whi[k * HID + h];
    g_Wh[k * NG + n + 1] = Whf[k * HID + h];
    g_Wh[k * NG + n + 2] = Whc[k * HID + h];
    g_Wh[k * NG + n + 3] = Who[k * HID + h];
    if (k < EMB) {
        g_Wx[k * NG + n + 0] = Wxi[k * HID + h];
        g_Wx[k * NG + n + 1] = Wxf[k * HID + h];
        g_Wx[k * NG + n + 2] = Wxc[k * HID + h];
        g_Wx[k * NG + n + 3] = Wxo[k * HID + h];
    }
    if (tid < HID) {
        g_bias[tid * 4 + 0] = bi[tid];
        g_bias[tid * 4 + 1] = bf[tid];
        g_bias[tid * 4 + 2] = bc[tid];
        g_bias[tid * 4 + 3] = bo[tid];
    }
}

// -------- GEMM 1: embedding gather + X@Wx + bias -> g_Gx --------
// grid (16, 256): blockIdx.y = timestep s, blockIdx.x = n-tile
__global__ __launch_bounds__(256) void xgemm_kernel(
    const int* __restrict__ X, const float* __restrict__ C_emb)
{
    __shared__ float As[8][132];
    __shared__ float Bs[8][128];
    __shared__ int sIdx[BATCH];
    const int t = threadIdx.x;
    const int s = blockIdx.y;
    const int n0 = blockIdx.x * 128;
    if (t < BATCH) sIdx[t] = X[t * SEQ + s];
    __syncthreads();

    const int ar = t >> 1, ak = (t & 1) * 4;
    const int bk = t >> 5, bn = (t & 31) * 4;
    const int rowB = (t >> 4) * 8, c4 = (t & 15) * 4;
    const float* Arow = C_emb + (size_t)sIdx[ar] * EMB + ak;
    const float* Bp = g_Wx + bk * NG + n0 + bn;

    u64 acc[8][4] = {};
    for (int k0 = 0; k0 < EMB; k0 += 8) {
        float4 av = *(const float4*)(Arow + k0);
        float4 bv = *(const float4*)(Bp + (size_t)k0 * NG);
        __syncthreads();
        As[ak + 0][ar] = av.x; As[ak + 1][ar] = av.y;
        As[ak + 2][ar] = av.z; As[ak + 3][ar] = av.w;
        *(float4*)&Bs[bk][bn] = bv;
        __syncthreads();
#pragma unroll
        for (int kk = 0; kk < 8; kk++) {
            float4 a0 = *(const float4*)&As[kk][rowB];
            float4 a1 = *(const float4*)&As[kk][rowB + 4];
            ulonglong2 b0 = *(const ulonglong2*)&Bs[kk][c4];
            ulonglong2 b1 = *(const ulonglong2*)&Bs[kk][c4 + 64];
            u64 ap[8];
            ap[0] = pack2(a0.x, a0.x); ap[1] = pack2(a0.y, a0.y);
            ap[2] = pack2(a0.z, a0.z); ap[3] = pack2(a0.w, a0.w);
            ap[4] = pack2(a1.x, a1.x); ap[5] = pack2(a1.y, a1.y);
            ap[6] = pack2(a1.z, a1.z); ap[7] = pack2(a1.w, a1.w);
#pragma unroll
            for (int i = 0; i < 8; i++) {
                fma2(acc[i][0], ap[i], b0.x);
                fma2(acc[i][1], ap[i], b0.y);
                fma2(acc[i][2], ap[i], b1.x);
                fma2(acc[i][3], ap[i], b1.y);
            }
        }
    }
#pragma unroll
    for (int i = 0; i < 8; i++) {
        float* orow = g_Gx + ((size_t)(s * BATCH + rowB + i)) * NG + n0;
        float2 v0 = unpack2(acc[i][0]), v1 = unpack2(acc[i][1]);
        float2 v2 = unpack2(acc[i][2]), v3 = unpack2(acc[i][3]);
        float4 bA = *(const float4*)&g_bias[n0 + c4];
        float4 bB = *(const float4*)&g_bias[n0 + c4 + 64];
        float4 w0 = make_float4(v0.x + bA.x, v0.y + bA.y, v1.x + bA.z, v1.y + bA.w);
        float4 w1 = make_float4(v2.x + bB.x, v2.y + bB.y, v3.x + bB.z, v3.y + bB.w);
        *(float4*)(orow + c4)      = w0;
        *(float4*)(orow + c4 + 64) = w1;
    }
}

// -------- persistent recurrent kernel --------
// 128 CTAs, 1/SM. GEMM phase: CTA (n-tile = bid&15, kz = (bid>>4)*64) does 128x128x64.
// Fuse phase: CTA bid owns h-chunk [bid*4, bid*4+4); thread owns batch row; C in regs.
__global__ __launch_bounds__(256, 1) void rnn_persistent()
{
    extern __shared__ float sdyn[];
    float* As = sdyn;             // [64][128] transposed A: As[k][b]
    float* Bs = sdyn + 64 * 128;  // [64][128] B tile (persistent across steps)

    const int t = threadIdx.x;
    const int bid = blockIdx.x;
    const int n0 = (bid & 15) * 128;
    const int kz = (bid >> 4) * 64;
    const int rowB = (t >> 4) * 8, c4 = (t & 15) * 4;

    // ---- load B tile ONCE (Wh constant across steps) ----
#pragma unroll
    for (int j = 0; j < 8; j++) {
        int f = t + j * 256;          // float4 index 0..2047
        int k = f >> 5;               // 0..63
        int n4 = (f & 31) * 4;
        *(float4*)&Bs[k * 128 + n4] = *(const float4*)&g_Wh[(size_t)(kz + k) * NG + n0 + n4];
    }

    // fuse-phase identity
    const int fb = t & 127;           // batch row
    const int fh = t >> 7;            // 0/1
    const int nbase = bid * 16 + fh * 8;
    const int h0 = bid * 4 + fh * 2;

    // init H_T[0] slice (rows bid*4 .. bid*4+3) and C regs
    *(float2*)&g_HT[0][bid * 512 + 2 * t] = make_float2(0.f, 0.f);
    float c0 = 0.f, c1 = 0.f;
    grid_bar();

    for (int step = 0; step < SEQ; step++) {
        // ---- stage A: As[k][b] = H_T[kz+k][b], contiguous float4 copies ----
        const float* HT = g_HT[step & 1];
#pragma unroll
        for (int j = 0; j < 8; j++) {
            int f = t + j * 256;
            int k = f >> 5;
            int r4 = (f & 31) * 4;
            float4 v = __ldcg((const float4*)&HT[(size_t)(kz + k) * BATCH + r4]);
            *(float4*)&As[k * 128 + r4] = v;
        }

        // ---- prefetch this step's Gx gates (DRAM) into regs: consumed in fuse,
        //      latency hidden behind the ~8K-cycle GEMM compute below ----
        const float* gxrow = g_Gx + ((size_t)(step * BATCH + fb)) * NG + nbase;
        float4 p0 = __ldcg((const float4*)gxrow);
        float4 p1 = __ldcg((const float4*)(gxrow + 4));

        __syncthreads();

        // ---- compute: 128x128x64 partial, FFMA2-bound ----
        u64 acc[8][4] = {};
#pragma unroll 8
        for (int kk = 0; kk < 64; kk++) {
            float4 a0 = *(const float4*)&As[kk * 128 + rowB];
            float4 a1 = *(const float4*)&As[kk * 128 + rowB + 4];
            ulonglong2 b0 = *(const ulonglong2*)&Bs[kk * 128 + c4];
            ulonglong2 b1 = *(const ulonglong2*)&Bs[kk * 128 + c4 + 64];
            u64 ap[8];
            ap[0] = pack2(a0.x, a0.x); ap[1] = pack2(a0.y, a0.y);
            ap[2] = pack2(a0.z, a0.z); ap[3] = pack2(a0.w, a0.w);
            ap[4] = pack2(a1.x, a1.x); ap[5] = pack2(a1.y, a1.y);
            ap[6] = pack2(a1.z, a1.z); ap[7] = pack2(a1.w, a1.w);
#pragma unroll
            for (int i = 0; i < 8; i++) {
                fma2(acc[i][0], ap[i], b0.x);
                fma2(acc[i][1], ap[i], b0.y);
                fma2(acc[i][2], ap[i], b1.x);
                fma2(acc[i][3], ap[i], b1.y);
            }
        }

        // ---- write partials (float4, coalesced) ----
#pragma unroll
        for (int i = 0; i < 8; i++) {
            float* orow = g_part + ((size_t)((bid >> 4) * BATCH + rowB + i)) * NG + n0;
            float2 v0 = unpack2(acc[i][0]), v1 = unpack2(acc[i][1]);
            float2 v2 = unpack2(acc[i][2]), v3 = unpack2(acc[i][3]);
            *(float4*)(orow + c4)      = make_float4(v0.x, v0.y, v1.x, v1.y);
            *(float4*)(orow + c4 + 64) = make_float4(v2.x, v2.y, v3.x, v3.y);
        }
        grid_bar();   // partials visible

        // ---- fuse: thread = (batch fb, h0/h0+1); C stays in registers ----
        {
#pragma unroll
            for (int z = 0; z < KSPLIT; z++) {
                const float* pr = g_part + ((size_t)(z * BATCH + fb)) * NG + nbase;
                float4 q0 = __ldcg((const float4*)pr);
                float4 q1 = __ldcg((const float4*)(pr + 4));
                p0.x += q0.x; p0.y += q0.y; p0.z += q0.z; p0.w += q0.w;
                p1.x += q1.x; p1.y += q1.y; p1.z += q1.z; p1.w += q1.w;
            }
            float I0 = fsig(p0.x), F0 = fsig(p0.y), T0 = ftanh(p0.z), O0 = fsig(p0.w);
            float I1 = fsig(p1.x), F1 = fsig(p1.y), T1 = ftanh(p1.z), O1 = fsig(p1.w);
            c0 = F0 * c0 + I0 * T0;
            c1 = F1 * c1 + I1 * T1;
            float* HTn = g_HT[(step + 1) & 1];
            HTn[(size_t)h0 * BATCH + fb]       = O0 * ftanh(c0);
            HTn[(size_t)(h0 + 1) * BATCH + fb] = O1 * ftanh(c1);
        }
        grid_bar();   // H visible before next step's GEMM
    }
}

// -------- GEMM 3: final projection H @ Whq + b_q -> out (H read from H_T) --------
__global__ __launch_bounds__(256) void out_gemm(
    const float* __restrict__ Whq, const float* __restrict__ bq, float* __restrict__ out)
{
    __shared__ float As[8][128];    // As[k][b] straight from H_T (contiguous)
    __shared__ float Bs[8][128];
    const int t = threadIdx.x;
    const int n0 = blockIdx.x * 128;
    const float* HT = g_HT[0];      // final H after 256 steps

    const int sk = t >> 5, sr4 = (t & 31) * 4;   // A-stage: one float4/thread
    const int bk = t >> 5, bn = (t & 31) * 4;    // B-stage
    const int rowB = (t >> 4) * 8, c4 = (t & 15) * 4;

    u64 acc[8][4] = {};
    for (int k0 = 0; k0 < HID; k0 += 8) {
        float4 av = *(const float4*)&HT[(size_t)(k0 + sk) * BATCH + sr4];
        float bv[4];
#pragma unroll
        for (int j = 0; j < 4; j++) {
            int c = n0 + bn + j;
            bv[j] = (c < N_CLASS) ? Whq[(size_t)(k0 + bk) * N_CLASS + c] : 0.f;
        }
        __syncthreads();
        *(float4*)&As[sk][sr4] = av;
        Bs[bk][bn + 0] = bv[0]; Bs[bk][bn + 1] = bv[1];
        Bs[bk][bn + 2] = bv[2]; Bs[bk][bn + 3] = bv[3];
        __syncthreads();
#pragma unroll
        for (int kk = 0; kk < 8; kk++) {
            float4 a0 = *(const float4*)&As[kk][rowB];
            float4 a1 = *(const float4*)&As[kk][rowB + 4];
            ulonglong2 b0 = *(const ulonglong2*)&Bs[kk][c4];
            ulonglong2 b1 = *(const ulonglong2*)&Bs[kk][c4 + 64];
            u64 ap[8];
            ap[0] = pack2(a0.x, a0.x); ap[1] = pack2(a0.y, a0.y);
            ap[2] = pack2(a0.z, a0.z); ap[3] = pack2(a0.w, a0.w);
            ap[4] = pack2(a1.x, a1.x); ap[5] = pack2(a1.y, a1.y);
            ap[6] = pack2(a1.z, a1.z); ap[7] = pack2(a1.w, a1.w);
#pragma unroll
            for (int i = 0; i < 8; i++) {
                fma2(acc[i][0], ap[i], b0.x);
                fma2(acc[i][1], ap[i], b0.y);
                fma2(acc[i][2], ap[i], b1.x);
                fma2(acc[i][3], ap[i], b1.y);
            }
        }
    }
#pragma unroll
    for (int i = 0; i < 8; i++) {
        float* orow = out + (size_t)(rowB + i) * N_CLASS;
        float2 v[4] = { unpack2(acc[i][0]), unpack2(acc[i][1]),
                        unpack2(acc[i][2]), unpack2(acc[i][3]) };
        float res[8] = { v[0].x, v[0].y, v[1].x, v[1].y, v[2].x, v[2].y, v[3].x, v[3].y };
#pragma unroll
        for (int j = 0; j < 8; j++) {
            int c = n0 + ((j < 4) ? (c4 + j) : (c4 + 60 + j));  // cols c4+0..3 and c4+64..67
            if (c < N_CLASS) orow[c] = res[j] + bq[c];
        }
    }
}

extern "C" void kernel_launch(void* const* d_in, const int* in_sizes, int n_in,
                              void* d_out, int out_size)
{
    const int*   X     = (const int*)d_in[0];
    const float* C_emb = (const float*)d_in[1];
    const float* W_xi  = (const float*)d_in[2];
    const float* W_xf  = (const float*)d_in[3];
    const float* W_xo  = (const float*)d_in[4];
    const float* W_xc  = (const float*)d_in[5];
    const float* W_hi  = (const float*)d_in[6];
    const float* W_hf  = (const float*)d_in[7];
    const float* W_ho  = (const float*)d_in[8];
    const float* W_hc  = (const float*)d_in[9];
    const float* b_i   = (const float*)d_in[10];
    const float* b_f   = (const float*)d_in[11];
    const float* b_o   = (const float*)d_in[12];
    const float* b_c   = (const float*)d_in[13];
    const float* W_hq  = (const float*)d_in[14];
    const float* b_q   = (const float*)d_in[15];
    float* out = (float*)d_out;

    // unconditional (no static guards): host-side attribute set, idempotent,
    // not a stream operation -> graph-capture safe
    cudaFuncSetAttribute(rnn_persistent,
                         cudaFuncAttributeMaxDynamicSharedMemorySize, 2 * 64 * 128 * 4);

    pack_kernel<<<(HID * HID) / 256, 256>>>(W_xi, W_xf, W_xo, W_xc,
                                            W_hi, W_hf, W_ho, W_hc,
                                            b_i, b_f, b_o, b_c);
    xgemm_kernel<<<dim3(NG / 128, SEQ), 256>>>(X, C_emb);
    rnn_persistent<<<NBLK, 256, 2 * 64 * 128 * 4>>>();
    out_gemm<<<(N_CLASS + 127) / 128, 256>>>(W_hq, b_q, out);
}